// round 10
// baseline (speedup 1.0000x reference)
#include <cuda_runtime.h>
#include <cstdint>

#define NPROB 512            // B*S = 32*16
#define MDIM  128
#define NDIM  256
#define EPSF  1e-6f
#define MUF   0.01f
#define KITER 30
#define LMAX  25
#define MASK_ALL 0x01FFFFFFu // 25 bits
#define TPB   256
#define CJ    5              // cached row-groups per warp (rows 0..39 in smem)
#define CROWS (CJ * 8)       // 40 rows cached
#define DYNSMEM (CROWS * NDIM * 4)
#define GRPS   16            // barrier tree: 16 groups of 32 CTAs
#define GRPSZ  32
#define GPAD   32            // 32 words = 128B between group slots (no line sharing)

typedef unsigned long long u64;

// Persistent device state
__device__ float    g_Aw[(size_t)NPROB * MDIM * NDIM]; // row-normalized A (64MB)
__device__ unsigned g_count;                            // setup barrier counter
__device__ unsigned g_sense;                            // setup barrier sense
// Two-level per-iteration barrier state (re-initialized each run by CTA 0)
__device__ unsigned g_gand[KITER][GRPS * GPAD];         // group AND masks
__device__ unsigned g_gcnt[KITER][GRPS * GPAD];         // group arrival counts
__device__ unsigned g_rand[KITER];                      // root AND mask
__device__ unsigned g_rcnt[KITER];                      // root arrival count
__device__ unsigned g_rel;                              // release: (epoch<<8)|stepbyte

// ---- packed f32x2 helpers (sm_103a FFMA2 path; per-element IEEE fp32) ----
__device__ __forceinline__ u64 pack2(float x, float y) {
    u64 r; asm("mov.b64 %0, {%1, %2};" : "=l"(r) : "f"(x), "f"(y)); return r;
}
__device__ __forceinline__ void unpack2(u64 v, float& x, float& y) {
    asm("mov.b64 {%0, %1}, %2;" : "=f"(x), "=f"(y) : "l"(v));
}
__device__ __forceinline__ u64 fma2(u64 a, u64 b, u64 c) {
    u64 d; asm("fma.rn.f32x2 %0, %1, %2, %3;" : "=l"(d) : "l"(a), "l"(b), "l"(c));
    return d;
}
__device__ __forceinline__ u64 mul2(u64 a, u64 b) {
    u64 d; asm("mul.rn.f32x2 %0, %1, %2;" : "=l"(d) : "l"(a), "l"(b));
    return d;
}

// NOTE: redux.sync.add.f32 is NOT supported on sm_103 (ptxas rejects it).
__device__ __forceinline__ float warp_allreduce_add(float v) {
#pragma unroll
    for (int o = 16; o; o >>= 1) v += __shfl_xor_sync(0xffffffffu, v, o);
    return v;
}

__device__ __forceinline__ float dot8(float4 a0, float4 a1, float4 b0, float4 b1) {
    float s = a0.x * b0.x + a0.y * b0.y + a0.z * b0.z + a0.w * b0.w;
    s += a1.x * b1.x + a1.y * b1.y + a1.z * b1.z + a1.w * b1.w;
    return s;
}

// Setup-only grid barrier (runs once). All NPROB CTAs co-resident:
// __launch_bounds__(256,4) + ~55KB smem/CTA -> 4 CTAs/SM * 148 = 592 >= 512.
#define GRID_BARRIER()                                                        \
    do {                                                                      \
        __syncthreads();                                                      \
        if (tid == 0) {                                                       \
            const unsigned target = sense ^ 1u;                               \
            __threadfence();                                                  \
            if (atomicAdd(&g_count, 1u) == NPROB - 1u) {                      \
                atomicExch(&g_count, 0u);                                     \
                __threadfence();                                              \
                atomicExch(&g_sense, target);                                 \
            } else {                                                          \
                while (*(volatile unsigned*)&g_sense != target)               \
                    __nanosleep(64);                                          \
            }                                                                 \
            sense = target;                                                   \
            __threadfence();                                                  \
        }                                                                     \
        __syncthreads();                                                      \
    } while (0)

__global__ void __launch_bounds__(TPB, 4)
persist_kernel(const float* __restrict__ xraw,
               const float* __restrict__ Ain,
               const float* __restrict__ bin,
               const float* __restrict__ lowin,
               float* __restrict__ out)
{
    extern __shared__ __align__(16) float sA[];   // CROWS x NDIM pinned A rows

    const int p    = blockIdx.x;
    const int tid  = threadIdx.x;
    const int lane = tid & 31;
    const int w    = tid >> 5;

    __shared__ __align__(16) float s_x[NDIM];
    __shared__ __align__(16) float s_grad[NDIM];
    __shared__ __align__(16) float s_lo[NDIM];
    __shared__ __align__(16) float s_xr[NDIM];
    __shared__ __align__(16) float s_bw[MDIM];
    __shared__ __align__(16) float s_Ax[MDIM];
    __shared__ __align__(16) float s_Ag[MDIM];
    __shared__ __align__(16) float s_v[MDIM];
    __shared__ __align__(16) float s_gb[8 * NDIM];   // per-warp gbar partials
    __shared__ unsigned s_mask;
    __shared__ float    s_step;
    __shared__ int      s_feas;

    const float* A  = Ain  + (size_t)p * MDIM * NDIM;
    float*       Aw = g_Aw + (size_t)p * MDIM * NDIM;

    // Read sense BEFORE first arrive (all CTAs read pre-flip value).
    unsigned sense = *(volatile unsigned*)&g_sense;

    // CTA 0 re-initializes per-iteration barrier state each run (covered by
    // setup barrier #0: writes -> threadfence -> arrive; others acquire after spin).
    if (p == 0) {
        for (int i = tid; i < KITER * GRPS * GPAD; i += TPB) {
            (&g_gand[0][0])[i] = MASK_ALL;
            (&g_gcnt[0][0])[i] = 0u;
        }
        if (tid < KITER) { g_rand[tid] = MASK_ALL; g_rcnt[tid] = 0u; }
    }

    if (tid < NDIM) {
        s_lo[tid] = lowin[p * NDIM + tid];
        s_xr[tid] = xraw[p * NDIM + tid];
    }
    if (tid == 0) s_feas = 1;
    __syncthreads();

    const int n0 = 4 * lane;
    const int n1 = 128 + 4 * lane;
    const float4 l0 = *(const float4*)(s_lo + n0);
    const float4 l1 = *(const float4*)(s_lo + n1);

    // per-lane line-search step: lane l tests step 2^-l (exact power of two)
    const float stepl = __uint_as_float((unsigned)(127 - lane) << 23);

    float* s_red = s_gb;   // alias: s_gb unused during setup

    // ---------------- setup: row-normalize, cache first 40 rows in smem -----
#pragma unroll 4
    for (int j = 0; j < 16; j++) {
        const int m = w + 8 * j;
        const float4 a0 = *(const float4*)(A + (size_t)m * NDIM + n0);
        const float4 a1 = *(const float4*)(A + (size_t)m * NDIM + n1);
        float ss = warp_allreduce_add(dot8(a0, a1, a0, a1));
        const float norm = fmaxf(sqrtf(ss), 1e-12f);
        float4 w0, w1;
        w0.x = a0.x / norm; w0.y = a0.y / norm; w0.z = a0.z / norm; w0.w = a0.w / norm;
        w1.x = a1.x / norm; w1.y = a1.y / norm; w1.z = a1.z / norm; w1.w = a1.w / norm;
        *(float4*)(Aw + (size_t)m * NDIM + n0) = w0;
        *(float4*)(Aw + (size_t)m * NDIM + n1) = w1;
        if (m < CROWS) {
            *(float4*)(sA + m * NDIM + n0) = w0;
            *(float4*)(sA + m * NDIM + n1) = w1;
        }
        float ad = (w0.x + w0.y + w0.z + w0.w) + (w1.x + w1.y + w1.z + w1.w);
        float sd = dot8(w0, w1, l0, l1);
        ad = warp_allreduce_add(ad);
        sd = warp_allreduce_add(sd);
        if (lane == 0) {
            const float bwm = bin[p * MDIM + m] / norm;
            s_bw[m]  = bwm;
            s_Ax[m]  = ad;          // temp: Ad
            s_red[m] = bwm - sd;    // temp: slack at lower
        }
    }
    __syncthreads();

    // t = max(0.5 * min_m ratio, 2*eps)
    if (tid < MDIM) {
        const float ad = s_Ax[tid];
        s_red[tid] = (ad > 0.f) ? (s_red[tid] / fmaxf(ad, 1e-12f))
                                : __int_as_float(0x7f800000); // +inf
    }
    __syncthreads();
    for (int off = 64; off >= 1; off >>= 1) {
        if (tid < off) s_red[tid] = fminf(s_red[tid], s_red[tid + off]);
        __syncthreads();
    }
    const float t = fmaxf(0.5f * s_red[0], 2.f * EPSF);
    __syncthreads();   // s_red (=s_gb) free again

    // feasibility of x = lower + t (fresh dots); also seeds s_Ax = A*x
    {
        float4 xq0, xq1;
        xq0.x = l0.x + t; xq0.y = l0.y + t; xq0.z = l0.z + t; xq0.w = l0.w + t;
        xq1.x = l1.x + t; xq1.y = l1.y + t; xq1.z = l1.z + t; xq1.w = l1.w + t;
#pragma unroll
        for (int j = 0; j < CJ; j++) {
            const int m = w + 8 * j;
            const float4 a0 = *(const float4*)(sA + m * NDIM + n0);
            const float4 a1 = *(const float4*)(sA + m * NDIM + n1);
            float d = warp_allreduce_add(dot8(a0, a1, xq0, xq1));
            if (lane == 0) {
                s_Ax[m] = d;
                if (!(d <= s_bw[m] - EPSF)) atomicAnd(&s_feas, 0);
            }
        }
#pragma unroll 4
        for (int j = CJ; j < 16; j++) {
            const int m = w + 8 * j;
            const float4 a0 = *(const float4*)(Aw + (size_t)m * NDIM + n0);
            const float4 a1 = *(const float4*)(Aw + (size_t)m * NDIM + n1);
            float d = warp_allreduce_add(dot8(a0, a1, xq0, xq1));
            if (lane == 0) {
                s_Ax[m] = d;
                if (!(d <= s_bw[m] - EPSF)) atomicAnd(&s_feas, 0);
            }
        }
        if (tid < NDIM) {
            const float xv = s_lo[tid] + t;
            if (!(xv >= s_lo[tid] + EPSF)) atomicAnd(&s_feas, 0);
        }
        __syncthreads();
        if (tid < NDIM) {
            float xv = s_lo[tid] + t;
            if (!s_feas) xv = 0.5f * (fmaxf(xv, 0.f) + s_lo[tid]);
            s_x[tid] = xv;
        }
        __syncthreads();
        if (!s_feas) {   // rare repair branch: recompute Ax of repaired x
            const float4 r0 = *(const float4*)(s_x + n0);
            const float4 r1 = *(const float4*)(s_x + n1);
            for (int j = 0; j < 16; j++) {
                const int m = w + 8 * j;
                const float* src = (j < CJ) ? (sA + m * NDIM)
                                            : (Aw + (size_t)m * NDIM);
                const float4 a0 = *(const float4*)(src + n0);
                const float4 a1 = *(const float4*)(src + n1);
                float d = warp_allreduce_add(dot8(a0, a1, r0, r1));
                if (lane == 0) s_Ax[m] = d;
            }
        }
    }

    GRID_BARRIER();   // barrier #0: barrier-state init + everyone's setup done

    // prime v and s_mask for iteration 0
    if (tid < MDIM)
        s_v[tid] = __fdividef(MUF, fmaxf(s_bw[tid] - s_Ax[tid], 1e-12f));
    if (tid == 0) s_mask = MASK_ALL;
    __syncthreads();

    // ---------------- main loop (incremental Ax: Ax_{k+1} = Ax_k - step*Ag) --
    for (int k = 0; k < KITER; k++) {
        // ---- pass G: gbar partials (pure streaming, no reduce/div) ---------
        u64 ga0 = 0ull, ga1 = 0ull, ga2 = 0ull, ga3 = 0ull;

#define PG_ROW(A0, A1, m)                                                     \
        do {                                                                  \
            const float v_ = s_v[m];                                          \
            const u64 vv = pack2(v_, v_);                                     \
            ga0 = fma2((A0).x, vv, ga0); ga1 = fma2((A0).y, vv, ga1);         \
            ga2 = fma2((A1).x, vv, ga2); ga3 = fma2((A1).y, vv, ga3);         \
        } while (0)

        // gmem rows ascending (j=CJ..15), deep unroll for MLP
#pragma unroll 8
        for (int j = CJ; j < 16; j++) {
            const int m = w + 8 * j;
            const ulonglong2 a0 = *(const ulonglong2*)(Aw + (size_t)m * NDIM + n0);
            const ulonglong2 a1 = *(const ulonglong2*)(Aw + (size_t)m * NDIM + n1);
            PG_ROW(a0, a1, m);
        }
        // smem-pinned rows
#pragma unroll
        for (int j = 0; j < CJ; j++) {
            const int m = w + 8 * j;
            const ulonglong2 a0 = *(const ulonglong2*)(sA + m * NDIM + n0);
            const ulonglong2 a1 = *(const ulonglong2*)(sA + m * NDIM + n1);
            PG_ROW(a0, a1, m);
        }
#undef PG_ROW

        {
            ulonglong2 t0; t0.x = ga0; t0.y = ga1;
            ulonglong2 t1; t1.x = ga2; t1.y = ga3;
            *(ulonglong2*)(s_gb + w * NDIM + n0) = t0;
            *(ulonglong2*)(s_gb + w * NDIM + n1) = t1;
        }
        __syncthreads();

        // grad + column-constraint mask bits (per-thread, serial + fast path)
        if (tid < NDIM) {
            float gb = 0.f;
#pragma unroll
            for (int j = 0; j < 8; j++) gb += s_gb[j * NDIM + tid];
            const float xv  = s_x[tid];
            const float lov = s_lo[tid];
            const float slo = fmaxf(xv - lov, 1e-12f);
            const float gr  = (xv - s_xr[tid]) + gb + __fdividef(MUF, slo);
            s_grad[tid] = gr;

            const float lim = lov + EPSF;
            if (!(gr <= 0.f && xv >= lim)) {   // fast path: all candidates pass
                unsigned mk = MASK_ALL;
                float st = 1.f;
#pragma unroll
                for (int l = 0; l < LMAX; l++) {
                    const float c = fmaf(-st, gr, xv);
                    if (!(c >= lim)) mk &= ~(1u << l);
                    st *= 0.5f;
                }
                if (mk != MASK_ALL) atomicAnd(&s_mask, mk);
            }
        }
        __syncthreads();

        // ---- pass A: Ag dots + row masks via lane-parallel ballot ----------
        const ulonglong2 gA = *(const ulonglong2*)(s_grad + n0);
        const ulonglong2 gB = *(const ulonglong2*)(s_grad + n1);
        unsigned wmask = MASK_ALL;

#define PA_ROW(A0, A1, m)                                                     \
        do {                                                                  \
            u64 s = mul2((A0).x, gA.x);                                       \
            s = fma2((A0).y, gA.y, s);                                        \
            s = fma2((A1).x, gB.x, s);                                        \
            s = fma2((A1).y, gB.y, s);                                        \
            float slo_, shi_; unpack2(s, slo_, shi_);                         \
            float ag = warp_allreduce_add(slo_ + shi_);                       \
            if (lane == 0) s_Ag[m] = ag;                                      \
            const float axc = fmaf(-stepl, ag, s_Ax[m]);                      \
            const unsigned bits =                                             \
                __ballot_sync(0xffffffffu, axc <= s_bw[m] - EPSF);            \
            wmask &= (bits | ~MASK_ALL);                                      \
        } while (0)

        // gmem rows DESCENDING (j=15..CJ): j=15 just read by pass G -> L2 hot
#pragma unroll 8
        for (int j = 15; j >= CJ; j--) {
            const int m = w + 8 * j;
            const ulonglong2 a0 = *(const ulonglong2*)(Aw + (size_t)m * NDIM + n0);
            const ulonglong2 a1 = *(const ulonglong2*)(Aw + (size_t)m * NDIM + n1);
            PA_ROW(a0, a1, m);
        }
        // smem-pinned rows
#pragma unroll
        for (int j = 0; j < CJ; j++) {
            const int m = w + 8 * j;
            const ulonglong2 a0 = *(const ulonglong2*)(sA + m * NDIM + n0);
            const ulonglong2 a1 = *(const ulonglong2*)(sA + m * NDIM + n1);
            PA_ROW(a0, a1, m);
        }
#undef PA_ROW

        if (lane == 0 && wmask != MASK_ALL) atomicAnd(&s_mask, wmask);
        __syncthreads();

        // ---- two-level global barrier; release word carries the step -------
        if (tid == 0) {
            const int grp = p >> 5;                      // 16 groups of 32
            unsigned* gand = &g_gand[k][grp * GPAD];
            unsigned* gcnt = &g_gcnt[k][grp * GPAD];
            atomicAnd(gand, s_mask);
            __threadfence();
            if (atomicAdd(gcnt, 1u) == GRPSZ - 1u) {     // group-last
                __threadfence();
                const unsigned gm = *(volatile unsigned*)gand;
                atomicAnd(&g_rand[k], gm);
                __threadfence();
                if (atomicAdd(&g_rcnt[k], 1u) == GRPS - 1u) {  // root-last
                    __threadfence();
                    const unsigned fin = *(volatile unsigned*)&g_rand[k] & MASK_ALL;
                    const unsigned sb = fin ? (unsigned)(__ffs(fin) - 1) : 0xFFu;
                    atomicExch(&g_rel, ((unsigned)(k + 2) << 8) | sb);
                }
            }
            const unsigned tgt = (unsigned)(k + 2);
            unsigned relv;
            while (((relv = *(volatile unsigned*)&g_rel) >> 8) != tgt)
                __nanosleep(32);
            const unsigned sb = relv & 0xFFu;
            s_step = (sb == 0xFFu) ? 0.f
                                   : __uint_as_float((127u - sb) << 23);
            s_mask = MASK_ALL;                            // reset for next iter
        }
        __syncthreads();

        // owner-thread updates: x, Ax, and v for the next iteration
        if (tid < NDIM) s_x[tid] = fmaf(-s_step, s_grad[tid], s_x[tid]);
        if (tid < MDIM) {
            const float nAx = fmaf(-s_step, s_Ag[tid], s_Ax[tid]);
            s_Ax[tid] = nAx;
            s_v[tid]  = __fdividef(MUF, fmaxf(s_bw[tid] - nAx, 1e-12f));
        }
        __syncthreads();   // s_v/s_x/s_Ax/s_mask visible to all for next iter
    }

    // finalize: relu(x) -> out
    if (tid < NDIM) out[p * NDIM + tid] = fmaxf(s_x[tid], 0.f);
}

extern "C" void kernel_launch(void* const* d_in, const int* in_sizes, int n_in,
                              void* d_out, int out_size) {
    // Identify inputs by size (dict order: x_raw, A, b, lower).
    int iA = 1, ib = 2, iv1 = 0, iv2 = 3;
    {
        int big = -1, small = -1, v1 = -1, v2 = -1;
        for (int i = 0; i < n_in; i++) {
            if (in_sizes[i] == NPROB * MDIM * NDIM) big = i;
            else if (in_sizes[i] == NPROB * MDIM)   small = i;
            else if (v1 < 0) v1 = i;
            else             v2 = i;
        }
        if (big >= 0 && small >= 0 && v1 >= 0 && v2 >= 0) {
            iA = big; ib = small; iv1 = v1; iv2 = v2;
        }
    }
    const float* xr  = (const float*)d_in[iv1];
    const float* A   = (const float*)d_in[iA];
    const float* b   = (const float*)d_in[ib];
    const float* low = (const float*)d_in[iv2];
    float* out = (float*)d_out;

    // Opt-in: static (~14.9KB) + dynamic (40KB) > 48KB default per-block limit.
    // Not a stream-ordered call -> does not enter / invalidate graph capture.
    cudaFuncSetAttribute(persist_kernel,
                         cudaFuncAttributeMaxDynamicSharedMemorySize, DYNSMEM);

    persist_kernel<<<NPROB, TPB, DYNSMEM>>>(xr, A, b, low, out);
}

// round 11
// speedup vs baseline: 1.1494x; 1.1494x over previous
#include <cuda_runtime.h>
#include <cstdint>

#define NPROB 512            // B*S = 32*16
#define MDIM  128
#define NDIM  256
#define EPSF  1e-6f
#define MUF   0.01f
#define KITER 30
#define LMAX  25
#define MASK_ALL 0x01FFFFFFu // 25 bits
#define TPB   256
#define CJ    5              // cached row-groups per warp (rows 0..39 in smem)
#define CROWS (CJ * 8)       // 40 rows cached
#define DYNSMEM (CROWS * NDIM * 4)

typedef unsigned long long u64;

// Persistent device state
__device__ float    g_Aw[(size_t)NPROB * MDIM * NDIM]; // row-normalized A (64MB)
__device__ unsigned g_count;                            // setup barrier counter
__device__ unsigned g_sense;                            // setup barrier sense
__device__ unsigned g_and[KITER];                       // per-iter AND of masks
__device__ unsigned g_cnt[KITER];                       // per-iter arrival count
__device__ unsigned g_rel;                              // release: (epoch<<8)|stepbyte

// ---- packed f32x2 helpers (sm_103a FFMA2 path; per-element IEEE fp32) ----
__device__ __forceinline__ u64 pack2(float x, float y) {
    u64 r; asm("mov.b64 %0, {%1, %2};" : "=l"(r) : "f"(x), "f"(y)); return r;
}
__device__ __forceinline__ void unpack2(u64 v, float& x, float& y) {
    asm("mov.b64 {%0, %1}, %2;" : "=f"(x), "=f"(y) : "l"(v));
}
__device__ __forceinline__ u64 fma2(u64 a, u64 b, u64 c) {
    u64 d; asm("fma.rn.f32x2 %0, %1, %2, %3;" : "=l"(d) : "l"(a), "l"(b), "l"(c));
    return d;
}
__device__ __forceinline__ u64 mul2(u64 a, u64 b) {
    u64 d; asm("mul.rn.f32x2 %0, %1, %2;" : "=l"(d) : "l"(a), "l"(b));
    return d;
}

// NOTE: redux.sync.add.f32 is NOT supported on sm_103 (ptxas rejects it).
__device__ __forceinline__ float warp_allreduce_add(float v) {
#pragma unroll
    for (int o = 16; o; o >>= 1) v += __shfl_xor_sync(0xffffffffu, v, o);
    return v;
}

__device__ __forceinline__ float dot8(float4 a0, float4 a1, float4 b0, float4 b1) {
    float s = a0.x * b0.x + a0.y * b0.y + a0.z * b0.z + a0.w * b0.w;
    s += a1.x * b1.x + a1.y * b1.y + a1.z * b1.z + a1.w * b1.w;
    return s;
}

// Setup-only grid barrier (runs once). All NPROB CTAs co-resident:
// __launch_bounds__(256,4) + ~55KB smem/CTA -> 4 CTAs/SM * 148 = 592 >= 512.
#define GRID_BARRIER()                                                        \
    do {                                                                      \
        __syncthreads();                                                      \
        if (tid == 0) {                                                       \
            const unsigned target = sense ^ 1u;                               \
            __threadfence();                                                  \
            if (atomicAdd(&g_count, 1u) == NPROB - 1u) {                      \
                atomicExch(&g_count, 0u);                                     \
                __threadfence();                                              \
                atomicExch(&g_sense, target);                                 \
            } else {                                                          \
                while (*(volatile unsigned*)&g_sense != target)               \
                    __nanosleep(64);                                          \
            }                                                                 \
            sense = target;                                                   \
            __threadfence();                                                  \
        }                                                                     \
        __syncthreads();                                                      \
    } while (0)

__global__ void __launch_bounds__(TPB, 4)
persist_kernel(const float* __restrict__ xraw,
               const float* __restrict__ Ain,
               const float* __restrict__ bin,
               const float* __restrict__ lowin,
               float* __restrict__ out)
{
    extern __shared__ __align__(16) float sA[];   // CROWS x NDIM pinned A rows

    const int p    = blockIdx.x;
    const int tid  = threadIdx.x;
    const int lane = tid & 31;
    const int w    = tid >> 5;

    __shared__ __align__(16) float s_x[NDIM];
    __shared__ __align__(16) float s_grad[NDIM];
    __shared__ __align__(16) float s_lo[NDIM];
    __shared__ __align__(16) float s_xr[NDIM];
    __shared__ __align__(16) float s_bw[MDIM];
    __shared__ __align__(16) float s_Ax[MDIM];
    __shared__ __align__(16) float s_Ag[MDIM];
    __shared__ __align__(16) float s_v[MDIM];
    __shared__ __align__(16) float s_gb[8 * NDIM];   // per-warp gbar partials
    __shared__ unsigned s_mask;
    __shared__ float    s_step;
    __shared__ int      s_feas;

    const float* A  = Ain  + (size_t)p * MDIM * NDIM;
    float*       Aw = g_Aw + (size_t)p * MDIM * NDIM;

    // Read sense BEFORE first arrive (all CTAs read pre-flip value).
    unsigned sense = *(volatile unsigned*)&g_sense;

    // CTA 0 re-initializes per-iteration barrier state each run (ordered by
    // setup barrier #0: writes -> threadfence -> arrive; others spin-acquire).
    if (p == 0) {
        if (tid < KITER) { g_and[tid] = MASK_ALL; g_cnt[tid] = 0u; }
        if (tid == 0)    g_rel = 0u;   // stale epochs can never match 1..KITER
    }

    if (tid < NDIM) {
        s_lo[tid] = lowin[p * NDIM + tid];
        s_xr[tid] = xraw[p * NDIM + tid];
    }
    if (tid == 0) s_feas = 1;
    __syncthreads();

    const int n0 = 4 * lane;
    const int n1 = 128 + 4 * lane;
    const float4 l0 = *(const float4*)(s_lo + n0);
    const float4 l1 = *(const float4*)(s_lo + n1);

    // per-lane line-search step: lane l tests step 2^-l (exact power of two)
    const float stepl = __uint_as_float((unsigned)(127 - lane) << 23);

    float* s_red = s_gb;   // alias: s_gb unused during setup

    // ---------------- setup: row-normalize, cache first 40 rows in smem -----
#pragma unroll 4
    for (int j = 0; j < 16; j++) {
        const int m = w + 8 * j;
        const float4 a0 = *(const float4*)(A + (size_t)m * NDIM + n0);
        const float4 a1 = *(const float4*)(A + (size_t)m * NDIM + n1);
        float ss = warp_allreduce_add(dot8(a0, a1, a0, a1));
        const float norm = fmaxf(sqrtf(ss), 1e-12f);
        float4 w0, w1;
        w0.x = a0.x / norm; w0.y = a0.y / norm; w0.z = a0.z / norm; w0.w = a0.w / norm;
        w1.x = a1.x / norm; w1.y = a1.y / norm; w1.z = a1.z / norm; w1.w = a1.w / norm;
        *(float4*)(Aw + (size_t)m * NDIM + n0) = w0;
        *(float4*)(Aw + (size_t)m * NDIM + n1) = w1;
        if (m < CROWS) {
            *(float4*)(sA + m * NDIM + n0) = w0;
            *(float4*)(sA + m * NDIM + n1) = w1;
        }
        float ad = (w0.x + w0.y + w0.z + w0.w) + (w1.x + w1.y + w1.z + w1.w);
        float sd = dot8(w0, w1, l0, l1);
        ad = warp_allreduce_add(ad);
        sd = warp_allreduce_add(sd);
        if (lane == 0) {
            const float bwm = bin[p * MDIM + m] / norm;
            s_bw[m]  = bwm;
            s_Ax[m]  = ad;          // temp: Ad
            s_red[m] = bwm - sd;    // temp: slack at lower
        }
    }
    __syncthreads();

    // t = max(0.5 * min_m ratio, 2*eps)
    if (tid < MDIM) {
        const float ad = s_Ax[tid];
        s_red[tid] = (ad > 0.f) ? (s_red[tid] / fmaxf(ad, 1e-12f))
                                : __int_as_float(0x7f800000); // +inf
    }
    __syncthreads();
    for (int off = 64; off >= 1; off >>= 1) {
        if (tid < off) s_red[tid] = fminf(s_red[tid], s_red[tid + off]);
        __syncthreads();
    }
    const float t = fmaxf(0.5f * s_red[0], 2.f * EPSF);
    __syncthreads();   // s_red (=s_gb) free again

    // feasibility of x = lower + t (fresh dots); also seeds s_Ax = A*x
    {
        float4 xq0, xq1;
        xq0.x = l0.x + t; xq0.y = l0.y + t; xq0.z = l0.z + t; xq0.w = l0.w + t;
        xq1.x = l1.x + t; xq1.y = l1.y + t; xq1.z = l1.z + t; xq1.w = l1.w + t;
#pragma unroll
        for (int j = 0; j < CJ; j++) {
            const int m = w + 8 * j;
            const float4 a0 = *(const float4*)(sA + m * NDIM + n0);
            const float4 a1 = *(const float4*)(sA + m * NDIM + n1);
            float d = warp_allreduce_add(dot8(a0, a1, xq0, xq1));
            if (lane == 0) {
                s_Ax[m] = d;
                if (!(d <= s_bw[m] - EPSF)) atomicAnd(&s_feas, 0);
            }
        }
#pragma unroll 4
        for (int j = CJ; j < 16; j++) {
            const int m = w + 8 * j;
            const float4 a0 = *(const float4*)(Aw + (size_t)m * NDIM + n0);
            const float4 a1 = *(const float4*)(Aw + (size_t)m * NDIM + n1);
            float d = warp_allreduce_add(dot8(a0, a1, xq0, xq1));
            if (lane == 0) {
                s_Ax[m] = d;
                if (!(d <= s_bw[m] - EPSF)) atomicAnd(&s_feas, 0);
            }
        }
        if (tid < NDIM) {
            const float xv = s_lo[tid] + t;
            if (!(xv >= s_lo[tid] + EPSF)) atomicAnd(&s_feas, 0);
        }
        __syncthreads();
        if (tid < NDIM) {
            float xv = s_lo[tid] + t;
            if (!s_feas) xv = 0.5f * (fmaxf(xv, 0.f) + s_lo[tid]);
            s_x[tid] = xv;
        }
        __syncthreads();
        if (!s_feas) {   // rare repair branch: recompute Ax of repaired x
            const float4 r0 = *(const float4*)(s_x + n0);
            const float4 r1 = *(const float4*)(s_x + n1);
            for (int j = 0; j < 16; j++) {
                const int m = w + 8 * j;
                const float* src = (j < CJ) ? (sA + m * NDIM)
                                            : (Aw + (size_t)m * NDIM);
                const float4 a0 = *(const float4*)(src + n0);
                const float4 a1 = *(const float4*)(src + n1);
                float d = warp_allreduce_add(dot8(a0, a1, r0, r1));
                if (lane == 0) s_Ax[m] = d;
            }
        }
    }

    GRID_BARRIER();   // barrier #0: barrier-state init + everyone's setup done

    // prime v and s_mask for iteration 0
    if (tid < MDIM)
        s_v[tid] = __fdividef(MUF, fmaxf(s_bw[tid] - s_Ax[tid], 1e-12f));
    if (tid == 0) s_mask = MASK_ALL;
    __syncthreads();

    // ---------------- main loop (incremental Ax: Ax_{k+1} = Ax_k - step*Ag) --
    for (int k = 0; k < KITER; k++) {
        // ---- pass G: gbar partials (pure streaming, no reduce/div) ---------
        u64 ga0 = 0ull, ga1 = 0ull, ga2 = 0ull, ga3 = 0ull;

#define PG_ROW(A0, A1, m)                                                     \
        do {                                                                  \
            const float v_ = s_v[m];                                          \
            const u64 vv = pack2(v_, v_);                                     \
            ga0 = fma2((A0).x, vv, ga0); ga1 = fma2((A0).y, vv, ga1);         \
            ga2 = fma2((A1).x, vv, ga2); ga3 = fma2((A1).y, vv, ga3);         \
        } while (0)

        // gmem rows ascending (j=CJ..15), deep unroll for MLP
#pragma unroll 8
        for (int j = CJ; j < 16; j++) {
            const int m = w + 8 * j;
            const ulonglong2 a0 = *(const ulonglong2*)(Aw + (size_t)m * NDIM + n0);
            const ulonglong2 a1 = *(const ulonglong2*)(Aw + (size_t)m * NDIM + n1);
            PG_ROW(a0, a1, m);
        }
        // smem-pinned rows
#pragma unroll
        for (int j = 0; j < CJ; j++) {
            const int m = w + 8 * j;
            const ulonglong2 a0 = *(const ulonglong2*)(sA + m * NDIM + n0);
            const ulonglong2 a1 = *(const ulonglong2*)(sA + m * NDIM + n1);
            PG_ROW(a0, a1, m);
        }
#undef PG_ROW

        {
            ulonglong2 t0; t0.x = ga0; t0.y = ga1;
            ulonglong2 t1; t1.x = ga2; t1.y = ga3;
            *(ulonglong2*)(s_gb + w * NDIM + n0) = t0;
            *(ulonglong2*)(s_gb + w * NDIM + n1) = t1;
        }
        __syncthreads();

        // grad + column-constraint mask bits (per-thread, serial + fast path)
        if (tid < NDIM) {
            float gb = 0.f;
#pragma unroll
            for (int j = 0; j < 8; j++) gb += s_gb[j * NDIM + tid];
            const float xv  = s_x[tid];
            const float lov = s_lo[tid];
            const float slo = fmaxf(xv - lov, 1e-12f);
            const float gr  = (xv - s_xr[tid]) + gb + __fdividef(MUF, slo);
            s_grad[tid] = gr;

            const float lim = lov + EPSF;
            if (!(gr <= 0.f && xv >= lim)) {   // fast path: all candidates pass
                unsigned mk = MASK_ALL;
                float st = 1.f;
#pragma unroll
                for (int l = 0; l < LMAX; l++) {
                    const float c = fmaf(-st, gr, xv);
                    if (!(c >= lim)) mk &= ~(1u << l);
                    st *= 0.5f;
                }
                if (mk != MASK_ALL) atomicAnd(&s_mask, mk);
            }
        }
        __syncthreads();

        // ---- pass A: Ag dots + row masks via lane-parallel ballot ----------
        const ulonglong2 gA = *(const ulonglong2*)(s_grad + n0);
        const ulonglong2 gB = *(const ulonglong2*)(s_grad + n1);
        unsigned wmask = MASK_ALL;

#define PA_ROW(A0, A1, m)                                                     \
        do {                                                                  \
            u64 s = mul2((A0).x, gA.x);                                       \
            s = fma2((A0).y, gA.y, s);                                        \
            s = fma2((A1).x, gB.x, s);                                        \
            s = fma2((A1).y, gB.y, s);                                        \
            float slo_, shi_; unpack2(s, slo_, shi_);                         \
            float ag = warp_allreduce_add(slo_ + shi_);                       \
            if (lane == 0) s_Ag[m] = ag;                                      \
            const float axc = fmaf(-stepl, ag, s_Ax[m]);                      \
            const unsigned bits =                                             \
                __ballot_sync(0xffffffffu, axc <= s_bw[m] - EPSF);            \
            wmask &= (bits | ~MASK_ALL);                                      \
        } while (0)

        // gmem rows DESCENDING (j=15..CJ)
#pragma unroll 8
        for (int j = 15; j >= CJ; j--) {
            const int m = w + 8 * j;
            const ulonglong2 a0 = *(const ulonglong2*)(Aw + (size_t)m * NDIM + n0);
            const ulonglong2 a1 = *(const ulonglong2*)(Aw + (size_t)m * NDIM + n1);
            PA_ROW(a0, a1, m);
        }
        // smem-pinned rows
#pragma unroll
        for (int j = 0; j < CJ; j++) {
            const int m = w + 8 * j;
            const ulonglong2 a0 = *(const ulonglong2*)(sA + m * NDIM + n0);
            const ulonglong2 a1 = *(const ulonglong2*)(sA + m * NDIM + n1);
            PA_ROW(a0, a1, m);
        }
#undef PA_ROW

        if (lane == 0 && wmask != MASK_ALL) atomicAnd(&s_mask, wmask);
        __syncthreads();

        // ---- flat global barrier; release word carries the step -------------
        if (tid == 0) {
            atomicAnd(&g_and[k], s_mask);
            __threadfence();
            if (atomicAdd(&g_cnt[k], 1u) == NPROB - 1u) {   // last arrival
                __threadfence();
                const unsigned fin = *(volatile unsigned*)&g_and[k] & MASK_ALL;
                const unsigned sb = fin ? (unsigned)(__ffs(fin) - 1) : 0xFFu;
                atomicExch(&g_rel, ((unsigned)(k + 1) << 8) | sb);
            }
            unsigned relv;
            while (((relv = *(volatile unsigned*)&g_rel) >> 8) != (unsigned)(k + 1))
                __nanosleep(32);
            const unsigned sb = relv & 0xFFu;
            s_step = (sb == 0xFFu) ? 0.f
                                   : __uint_as_float((127u - sb) << 23);
            s_mask = MASK_ALL;                // reset for next iteration
        }
        __syncthreads();

        // owner-thread updates: x, Ax, and v for the next iteration
        if (tid < NDIM) s_x[tid] = fmaf(-s_step, s_grad[tid], s_x[tid]);
        if (tid < MDIM) {
            const float nAx = fmaf(-s_step, s_Ag[tid], s_Ax[tid]);
            s_Ax[tid] = nAx;
            s_v[tid]  = __fdividef(MUF, fmaxf(s_bw[tid] - nAx, 1e-12f));
        }
        __syncthreads();   // s_v/s_x/s_mask visible to all for next iteration
    }

    // finalize: relu(x) -> out
    if (tid < NDIM) out[p * NDIM + tid] = fmaxf(s_x[tid], 0.f);
}

extern "C" void kernel_launch(void* const* d_in, const int* in_sizes, int n_in,
                              void* d_out, int out_size) {
    // Identify inputs by size (dict order: x_raw, A, b, lower).
    int iA = 1, ib = 2, iv1 = 0, iv2 = 3;
    {
        int big = -1, small = -1, v1 = -1, v2 = -1;
        for (int i = 0; i < n_in; i++) {
            if (in_sizes[i] == NPROB * MDIM * NDIM) big = i;
            else if (in_sizes[i] == NPROB * MDIM)   small = i;
            else if (v1 < 0) v1 = i;
            else             v2 = i;
        }
        if (big >= 0 && small >= 0 && v1 >= 0 && v2 >= 0) {
            iA = big; ib = small; iv1 = v1; iv2 = v2;
        }
    }
    const float* xr  = (const float*)d_in[iv1];
    const float* A   = (const float*)d_in[iA];
    const float* b   = (const float*)d_in[ib];
    const float* low = (const float*)d_in[iv2];
    float* out = (float*)d_out;

    // Opt-in: static (~14.9KB) + dynamic (40KB) > 48KB default per-block limit.
    // Not a stream-ordered call -> does not enter / invalidate graph capture.
    cudaFuncSetAttribute(persist_kernel,
                         cudaFuncAttributeMaxDynamicSharedMemorySize, DYNSMEM);

    persist_kernel<<<NPROB, TPB, DYNSMEM>>>(xr, A, b, low, out);
}